// round 1
// baseline (speedup 1.0000x reference)
#include <cuda_runtime.h>

#define EPSBN 1e-5f

static const int BB = 8;
static const int HH = 128;
static const int WW = 128;
static const int HW = 16384;         // 128*128
static const int C1 = 16, C2 = 64, C3 = 32;
static const float INV_N = 1.0f / 131072.0f;   // 1/(B*H*W)

// ---------------- scratch (static __device__, no allocation) ----------------
__device__ float g_t1[BB * C1 * HW];     // conv1 out (pre-BN1)
__device__ float g_t2[BB * C2 * HW];     // conv2 out (pre-BN2)
__device__ float g_feat[BB * C3 * HW];   // conv3 out (hooked feature)

__device__ float g_s1[C1], g_q1[C1], g_mu1[C1], g_iv1[C1], g_sc1[C1], g_sh1[C1];
__device__ float g_s2[C2], g_q2[C2], g_mu2[C2], g_iv2[C2], g_sc2[C2], g_sh2[C2];
__device__ float g_s3[C3], g_q3[C3], g_mu3[C3], g_iv3[C3], g_sc3[C3], g_sh3[C3];

__device__ float g_qpool[BB * C3 * 64];  // pooled x-hat (b, ch, 8, 8)
__device__ float g_gp[BB * 2 * 2048];    // grad wrt pooled features
__device__ float g_M1[BB * 2 * C3];
__device__ float g_M2[BB * 2 * C3];

// ---------------- kernels ----------------

__global__ void zero_stats_kernel() {
    int t = threadIdx.x;
    if (t < C1) { g_s1[t] = 0.f; g_q1[t] = 0.f; }
    if (t < C2) { g_s2[t] = 0.f; g_q2[t] = 0.f; }
    if (t < C3) { g_s3[t] = 0.f; g_q3[t] = 0.f; }
}

// conv1: x(8,3,128,128) -> g_t1(8,16,128,128). kernel 2x2, pad lo=0 hi=1.
__global__ void conv1_kernel(const float* __restrict__ x,
                             const float* __restrict__ w1,
                             const float* __restrict__ b1) {
    int idx = blockIdx.x * 256 + threadIdx.x;           // 2,097,152 total
    int pix = idx & (HW - 1);
    int c = (idx >> 14) & 15;
    int b = idx >> 18;
    int h = pix >> 7, w = pix & 127;
    float acc = b1[c];
    bool he = (h + 1 < HH), we = (w + 1 < WW);
#pragma unroll
    for (int ic = 0; ic < 3; ic++) {
        const float* xp = x + (b * 3 + ic) * HW;
        const float* wp = w1 + (c * 3 + ic) * 4;
        float x00 = xp[h * WW + w];
        float x01 = we ? xp[h * WW + w + 1] : 0.f;
        float x10 = he ? xp[(h + 1) * WW + w] : 0.f;
        float x11 = (he && we) ? xp[(h + 1) * WW + w + 1] : 0.f;
        acc += x00 * wp[0] + x01 * wp[1] + x10 * wp[2] + x11 * wp[3];
    }
    g_t1[idx] = acc;
}

// per-channel sum / sumsq. WHICH: 0=t1(16ch), 1=t2(64ch), 2=feat(32ch)
template <int WHICH>
__global__ void stats_kernel() {
    const float* src; float* sum; float* sq; int C;
    if (WHICH == 0) { src = g_t1;   sum = g_s1; sq = g_q1; C = C1; }
    else if (WHICH == 1) { src = g_t2; sum = g_s2; sq = g_q2; C = C2; }
    else { src = g_feat; sum = g_s3; sq = g_q3; C = C3; }
    int c = blockIdx.x;
    int b = blockIdx.y;                 // 8
    const float* p = src + (b * C + c) * HW;
    float s = 0.f, s2 = 0.f;
    for (int i = threadIdx.x; i < HW; i += 256) {
        float v = p[i];
        s += v; s2 += v * v;
    }
#pragma unroll
    for (int o = 16; o; o >>= 1) {
        s  += __shfl_down_sync(0xFFFFFFFFu, s, o);
        s2 += __shfl_down_sync(0xFFFFFFFFu, s2, o);
    }
    __shared__ float ws[8], ws2[8];
    int lane = threadIdx.x & 31, wid = threadIdx.x >> 5;
    if (lane == 0) { ws[wid] = s; ws2[wid] = s2; }
    __syncthreads();
    if (threadIdx.x == 0) {
        float t = 0.f, t2 = 0.f;
#pragma unroll
        for (int i = 0; i < 8; i++) { t += ws[i]; t2 += ws2[i]; }
        atomicAdd(&sum[c], t);
        atomicAdd(&sq[c], t2);
    }
}

// finalize BN params for stage WHICH; g/beta passed from inputs
template <int WHICH>
__global__ void finalize_kernel(const float* __restrict__ g,
                                const float* __restrict__ beta) {
    const float* sum; const float* sq; float *mu, *iv, *sc, *sh; int C;
    if (WHICH == 0) { sum = g_s1; sq = g_q1; mu = g_mu1; iv = g_iv1; sc = g_sc1; sh = g_sh1; C = C1; }
    else if (WHICH == 1) { sum = g_s2; sq = g_q2; mu = g_mu2; iv = g_iv2; sc = g_sc2; sh = g_sh2; C = C2; }
    else { sum = g_s3; sq = g_q3; mu = g_mu3; iv = g_iv3; sc = g_sc3; sh = g_sh3; C = C3; }
    int c = threadIdx.x;
    if (c < C) {
        float m = sum[c] * INV_N;
        float v = sq[c] * INV_N - m * m;
        float ivv = rsqrtf(v + EPSBN);
        mu[c] = m; iv[c] = ivv;
        float s = g[c] * ivv;
        sc[c] = s;
        sh[c] = beta[c] - m * s;
    }
}

// tiled conv with BN folded into the input load.
// CIN==16: g_t1 (scaled by sc1/sh1) -> g_t2 ; CIN==64: g_t2 (sc2/sh2) -> g_feat
template <int CIN, int COUT>
__global__ void conv_tiled_kernel(const float* __restrict__ wgt,
                                  const float* __restrict__ bias) {
    const int ICC = 16, OCC = 16, T = 16;
    const float* in;  float* out;  const float* scale;  const float* shift;
    if (CIN == 16) { in = g_t1; out = g_t2;  scale = g_sc1; shift = g_sh1; }
    else           { in = g_t2; out = g_feat; scale = g_sc2; shift = g_sh2; }

    __shared__ float s_in[ICC][T + 1][T + 2];   // [16][17][18]
    __shared__ float s_w[OCC][ICC][2][2];       // 1024 floats

    int tid = threadIdx.x;
    int tx = tid & 15, ty = tid >> 4;
    int zb = blockIdx.z;
    int b = zb / (COUT / OCC);
    int ocb = zb % (COUT / OCC);
    int h0 = blockIdx.y * T, w0 = blockIdx.x * T;

    float acc[OCC];
#pragma unroll
    for (int i = 0; i < OCC; i++) acc[i] = 0.f;

#pragma unroll 1
    for (int icc = 0; icc < CIN / ICC; icc++) {
        // load weight chunk: [OCC][ICC][2][2] contiguous slice
        for (int i = tid; i < OCC * ICC * 4; i += 256) {
            int oc = i >> 6;
            int rem = i & 63;
            ((float*)s_w)[i] = wgt[(ocb * OCC + oc) * (CIN * 4) + icc * 64 + rem];
        }
        // load 17x17 input halo tile for 16 channels, BN applied, zero pad hi
        for (int i = tid; i < ICC * 289; i += 256) {
            int icl = i / 289;
            int r = i - icl * 289;
            int iy = r / 17, ix = r - iy * 17;
            int gh = h0 + iy, gw = w0 + ix;
            int c = icc * ICC + icl;
            float v = 0.f;
            if (gh < HH && gw < WW)
                v = scale[c] * in[((b * CIN + c) * HH + gh) * WW + gw] + shift[c];
            s_in[icl][iy][ix] = v;
        }
        __syncthreads();
#pragma unroll
        for (int icl = 0; icl < ICC; icl++) {
            float r00 = s_in[icl][ty][tx];
            float r01 = s_in[icl][ty][tx + 1];
            float r10 = s_in[icl][ty + 1][tx];
            float r11 = s_in[icl][ty + 1][tx + 1];
#pragma unroll
            for (int oc = 0; oc < OCC; oc++) {
                acc[oc] += r00 * s_w[oc][icl][0][0] + r01 * s_w[oc][icl][0][1]
                         + r10 * s_w[oc][icl][1][0] + r11 * s_w[oc][icl][1][1];
            }
        }
        __syncthreads();
    }
    int h = h0 + ty, w = w0 + tx;
#pragma unroll
    for (int oc = 0; oc < OCC; oc++) {
        int c = ocb * OCC + oc;
        out[((b * COUT + c) * HH + h) * WW + w] = acc[oc] + bias[c];
    }
}

// pooled x-hat: q[b,ch,wi,wj] = (mean_window(feat) - mu)*inv   grid(8,32) x 256
__global__ void pool_kernel() {
    int b = blockIdx.x, ch = blockIdx.y;
    const float* p = g_feat + (b * C3 + ch) * HW;
    int t = threadIdx.x;
    int widx = t & 63;
    int part = t >> 6;                  // 0..3
    int wi = widx >> 3, wj = widx & 7;
    int r0 = wi * 16 + part * 4;
    int cb = wj * 16;
    float s = 0.f;
#pragma unroll
    for (int r = 0; r < 4; r++) {
        const float4* row = (const float4*)(p + (r0 + r) * WW + cb);
#pragma unroll
        for (int k = 0; k < 4; k++) {
            float4 v = row[k];
            s += v.x + v.y + v.z + v.w;
        }
    }
    __shared__ float sm[256];
    sm[t] = s;
    __syncthreads();
    if (t < 64) {
        float tot = sm[t] + sm[t + 64] + sm[t + 128] + sm[t + 192];
        g_qpool[(b * C3 + ch) * 64 + t] = (tot * (1.f / 256.f) - g_mu3[ch]) * g_iv3[ch];
    }
}

// head: z, y, softmax/relu backward coeffs, gp, M1, M2. One block, 256 thr.
__global__ void head_kernel(const float* __restrict__ g3,
                            const float* __restrict__ bt3,
                            const float* __restrict__ lw,
                            const float* __restrict__ lb,
                            float* __restrict__ yout) {
    __shared__ float s_z[16];
    __shared__ float s_a[8][2][2];
    int t = threadIdx.x;
    int warp = t >> 5, lane = t & 31;

    // z[b,k] = sum_f (g3*q + bt3)*lw[k,f] + lb[k]   (16 dot products of 2048)
    for (int pp = 0; pp < 2; pp++) {
        int pair = warp * 2 + pp;
        int b = pair >> 1, k = pair & 1;
        float s = 0.f;
        for (int f = lane; f < 2048; f += 32) {
            int ch = f >> 6;
            s += (g3[ch] * g_qpool[b * 2048 + f] + bt3[ch]) * lw[k * 2048 + f];
        }
#pragma unroll
        for (int o = 16; o; o >>= 1) s += __shfl_down_sync(0xFFFFFFFFu, s, o);
        if (lane == 0) s_z[pair] = s + lb[k];
    }
    __syncthreads();

    if (t < 8) {
        int b = t;
        float z0 = s_z[b * 2 + 0], z1 = s_z[b * 2 + 1];
        float r0 = z0 > 0.f ? z0 : 0.f, r1 = z1 > 0.f ? z1 : 0.f;
        float m = fmaxf(r0, r1);
        float e0 = expf(r0 - m), e1 = expf(r1 - m);
        float is = 1.f / (e0 + e1);
        float y0 = e0 * is, y1 = e1 * is;
        yout[b * 2 + 0] = y0;
        yout[b * 2 + 1] = y1;
        float m0 = z0 > 0.f ? 1.f : 0.f, m1 = z1 > 0.f ? 1.f : 0.f;
        s_a[b][0][0] = y0 * (1.f - y0) * m0;
        s_a[b][0][1] = y0 * (-y1) * m1;
        s_a[b][1][0] = y1 * (-y0) * m0;
        s_a[b][1][1] = y1 * (1.f - y1) * m1;
    }
    __syncthreads();

    // gp[b,c,f] = a0*lw[0,f] + a1*lw[1,f]
    for (int i = t; i < 8 * 2 * 2048; i += 256) {
        int f = i & 2047;
        int c = (i >> 11) & 1;
        int b = i >> 12;
        g_gp[i] = s_a[b][c][0] * lw[f] + s_a[b][c][1] * lw[2048 + f];
    }
    __syncthreads();

    // M1[b,c,ch] = sum_w gp / N ; M2 = sum_w gp*q / N
    for (int g = t; g < 8 * 2 * 32; g += 256) {
        int ch = g & 31;
        int c = (g >> 5) & 1;
        int b = g >> 6;
        const float* gpp = g_gp + (b * 2 + c) * 2048 + ch * 64;
        const float* qq = g_qpool + (b * 32 + ch) * 64;
        float s1 = 0.f, s2 = 0.f;
#pragma unroll
        for (int j = 0; j < 64; j++) {
            float gv = gpp[j];
            s1 += gv;
            s2 += gv * qq[j];
        }
        g_M1[g] = s1 * INV_N;
        g_M2[g] = s2 * INV_N;
    }
}

// cam[b,c,h,w] = sum_ch feat * (g3*inv) * (gp/256 - M1 - xhat*M2)
__global__ void cam_kernel(const float* __restrict__ g3,
                           float* __restrict__ out) {
    int idx = blockIdx.x * 256 + threadIdx.x;   // 131072
    int pix = idx & (HW - 1);
    int b = idx >> 14;
    int h = pix >> 7, w = pix & 127;
    int blk = ((h >> 4) << 3) + (w >> 4);
    float cam0 = 0.f, cam1 = 0.f;
#pragma unroll 8
    for (int ch = 0; ch < 32; ch++) {
        float v = g_feat[(b * 32 + ch) * HW + pix];
        float iv = g_iv3[ch];
        float xh = (v - g_mu3[ch]) * iv;
        float gi = g3[ch] * iv;
        int f = (ch << 6) + blk;
        float gp0 = g_gp[(b * 2 + 0) * 2048 + f];
        float gp1 = g_gp[(b * 2 + 1) * 2048 + f];
        int mb = b * 64 + ch;
        cam0 += v * gi * (gp0 * (1.f / 256.f) - g_M1[mb] - xh * g_M2[mb]);
        cam1 += v * gi * (gp1 * (1.f / 256.f) - g_M1[mb + 32] - xh * g_M2[mb + 32]);
    }
    out[16 + (b * 2 + 0) * HW + pix] = cam0;
    out[16 + (b * 2 + 1) * HW + pix] = cam1;
}

// ---------------- launch ----------------
extern "C" void kernel_launch(void* const* d_in, const int* in_sizes, int n_in,
                              void* d_out, int out_size) {
    const float* x   = (const float*)d_in[0];
    const float* w1  = (const float*)d_in[1];
    const float* b1  = (const float*)d_in[2];
    const float* g1  = (const float*)d_in[3];
    const float* bt1 = (const float*)d_in[4];
    const float* w2  = (const float*)d_in[5];
    const float* b2  = (const float*)d_in[6];
    const float* g2  = (const float*)d_in[7];
    const float* bt2 = (const float*)d_in[8];
    const float* w3  = (const float*)d_in[9];
    const float* b3  = (const float*)d_in[10];
    const float* g3  = (const float*)d_in[11];
    const float* bt3 = (const float*)d_in[12];
    const float* lw  = (const float*)d_in[13];
    const float* lb  = (const float*)d_in[14];
    float* out = (float*)d_out;

    zero_stats_kernel<<<1, 64>>>();

    conv1_kernel<<<(BB * C1 * HW) / 256, 256>>>(x, w1, b1);
    stats_kernel<0><<<dim3(C1, 8), 256>>>();
    finalize_kernel<0><<<1, 64>>>(g1, bt1);

    conv_tiled_kernel<16, 64><<<dim3(8, 8, BB * 4), 256>>>(w2, b2);
    stats_kernel<1><<<dim3(C2, 8), 256>>>();
    finalize_kernel<1><<<1, 64>>>(g2, bt2);

    conv_tiled_kernel<64, 32><<<dim3(8, 8, BB * 2), 256>>>(w3, b3);
    stats_kernel<2><<<dim3(C3, 8), 256>>>();
    finalize_kernel<2><<<1, 64>>>(g3, bt3);

    pool_kernel<<<dim3(8, 32), 256>>>();
    head_kernel<<<1, 256>>>(g3, bt3, lw, lb, out);
    cam_kernel<<<(BB * HW) / 256, 256>>>(g3, out);
}